// round 16
// baseline (speedup 1.0000x reference)
#include <cuda_runtime.h>

#define BB 256
#define SS 4096
#define HH 64
#define NG 256   // 4*H gates

// Scratch (allocation-free: static device globals)
__device__ float g_buf0[(size_t)BB * SS * HH];
__device__ float g_buf1[(size_t)BB * SS * HH];
__device__ float g_xg[(size_t)BB * SS * NG];   // gate-interleaved: [b,s,hh*4+q]

typedef unsigned long long ull;

// ---- packed f32x2 helpers (FFMA2 path, sm_103a) ----
__device__ __forceinline__ ull pk2(float lo, float hi) {
    ull r; asm("mov.b64 %0,{%1,%2};" : "=l"(r) : "f"(lo), "f"(hi)); return r;
}
__device__ __forceinline__ void upk2(ull v, float& lo, float& hi) {
    asm("mov.b64 {%0,%1},%2;" : "=f"(lo), "=f"(hi) : "l"(v));
}
__device__ __forceinline__ ull ffma2(ull a, ull b, ull c) {
    ull d; asm("fma.rn.f32x2 %0,%1,%2,%3;" : "=l"(d) : "l"(a), "l"(b), "l"(c)); return d;
}

// single-op MUFU tanh (sm_75+). R13/R14 measured: total rel_err stays ~3e-6.
__device__ __forceinline__ float tanh_mufu(float x) {
    float r; asm("tanh.approx.f32 %0, %1;" : "=f"(r) : "f"(x)); return r;
}

// Named barrier over one batch's 128 threads (4 warps). ids 1,2.
#define BATCH_BAR(bl) asm volatile("bar.sync %0, 128;" :: "r"((bl) + 1) : "memory")

// ============================================================================
// xgemm, occ-2 + MLP-8 burst edition. R15 ncu: fma=44%, issue=36% — LDS and
// FFMA2 pipes serializing on load-use dependency. Fix (same as scan's R10
// win): 4 phases of {8 independent LDS.128 burst -> 16 ffma2} per row-pair.
// Accumulation k-order unchanged -> bitwise-identical output.
// ============================================================================
__global__ __launch_bounds__(256, 2)
void xgemm(const float* __restrict__ hs, const float* __restrict__ Wih,
           const float* __restrict__ bih, const float* __restrict__ bhh,
           float* __restrict__ xg) {
    const int gq = threadIdx.x;
    const int q = gq & 3, hh = gq >> 2;
    const int row = q * HH + hh;
    const int pair = blockIdx.x >> 3;          // 0..127 batch pair
    const int slice = blockIdx.x & 7;          // 0..7 s-slice
    const int b0 = pair * 2;
    const int s0 = slice * (SS / 8);           // 512-step slice

    __shared__ float4 sh[2][16][16];   // [parity][chunk row][16 float4]

    ull w[32];
    {
        const float4* Wr = reinterpret_cast<const float4*>(Wih + row * HH);
#pragma unroll
        for (int k = 0; k < 16; k++) {
            float4 v = Wr[k];
            w[2 * k] = pk2(v.x, v.y);
            w[2 * k + 1] = pk2(v.z, v.w);
        }
    }
    const float bias = bih[row] + bhh[row];

    const int bb = gq >> 7, so = (gq >> 4) & 7, qq = gq & 15;
    const size_t ldb = ((size_t)(b0 + bb) * SS + s0 + so) * 16 + qq;  // float4 units
    const float4* hs4 = reinterpret_cast<const float4*>(hs);

    sh[0][bb * 8 + so][qq] = hs4[ldb];   // prime chunk 0

    int p = 0;
    const int NCH = (SS / 8) / 8;  // 64 chunks per slice
    for (int ch = 0; ch < NCH; ++ch) {
        __syncthreads();
        float4 nxt;
        if (ch + 1 < NCH) nxt = hs4[ldb + (size_t)(ch + 1) * 128];

#pragma unroll
        for (int rp = 0; rp < 8; ++rp) {
            const int r0 = 2 * rp, r1 = r0 + 1;
            ull a0 = pk2(bias, 0.f);
            ull a1 = pk2(bias, 0.f);
            const ulonglong2* v0 = reinterpret_cast<const ulonglong2*>(sh[p][r0]);
            const ulonglong2* v1 = reinterpret_cast<const ulonglong2*>(sh[p][r1]);
            // 4 phases: burst 8 independent LDS.128 (MLP 8), then 16 ffma2.
            // k ascends within each accumulator -> bitwise-identical to R15.
#pragma unroll
            for (int ph = 0; ph < 4; ++ph) {
                ulonglong2 b0v[4], b1v[4];
#pragma unroll
                for (int k = 0; k < 4; k++) {
                    b0v[k] = v0[ph * 4 + k];
                    b1v[k] = v1[ph * 4 + k];
                }
#pragma unroll
                for (int k = 0; k < 4; k++) {
                    const int kk = ph * 4 + k;
                    a0 = ffma2(w[2 * kk], b0v[k].x, a0);
                    a0 = ffma2(w[2 * kk + 1], b0v[k].y, a0);
                    a1 = ffma2(w[2 * kk], b1v[k].x, a1);
                    a1 = ffma2(w[2 * kk + 1], b1v[k].y, a1);
                }
            }
            float l, h;
            upk2(a0, l, h); float sA = l + h;
            upk2(a1, l, h); float sB = l + h;
            xg[((size_t)(b0 + (r0 >> 3)) * SS + s0 + (size_t)ch * 8 + (r0 & 7)) * NG + gq] = sA;
            xg[((size_t)(b0 + (r1 >> 3)) * SS + s0 + (size_t)ch * 8 + (r1 & 7)) * NG + gq] = sB;
        }
        if (ch + 1 < NCH) sh[p ^ 1][bb * 8 + so][qq] = nxt;
        p ^= 1;
    }
}

// ============================================================================
// LSTM scan = BYTE-EXACT R14/R15 champion (no changes).
// ============================================================================
template <bool L0>
__global__ __launch_bounds__(256, 1)
void lstm_scan(const float* __restrict__ xin,   // L0: x [B,S,1]; else xg [B,S,256]
               const float* __restrict__ Wih,   // L0 only: [256,1]
               const float* __restrict__ Whh,
               const float* __restrict__ bih, const float* __restrict__ bhh,
               float* __restrict__ hsout,
               float* __restrict__ hn, float* __restrict__ cn) {
    const int j = threadIdx.x;
    const int p = j & 1;
    const int hh = (j >> 1) & 63;
    const int b = j >> 7;
    const int b0 = blockIdx.x * 2;
    const int row0 = p * 128 + hh;        // p0: i-row ; p1: g-row
    const int row1 = p * 128 + 64 + hh;   // p0: f-row ; p1: o-row

    __shared__ float4 sh_h[2][2][16];   // [parity][b][64 floats]

    ull wA[32], wB[32];
    {
        const float4* Wr = reinterpret_cast<const float4*>(Whh + row0 * HH);
#pragma unroll
        for (int k = 0; k < 16; k++) {
            float4 v = Wr[k];
            wA[2 * k] = pk2(v.x, v.y);
            wA[2 * k + 1] = pk2(v.z, v.w);
        }
        const float4* Wr2 = reinterpret_cast<const float4*>(Whh + row1 * HH);
#pragma unroll
        for (int k = 0; k < 16; k++) {
            float4 v = Wr2[k];
            wB[2 * k] = pk2(v.x, v.y);
            wB[2 * k + 1] = pk2(v.z, v.w);
        }
    }
    float w0A = 0.f, w0B = 0.f, biasA = 0.f, biasB = 0.f;
    if (L0) {
        w0A = Wih[row0]; w0B = Wih[row1];
        biasA = bih[row0] + bhh[row0];
        biasB = bih[row1] + bhh[row1];
    }
    // activation constants: A0 = ma*tanh(sa*g0) + da
    //   p0 (i-gate, sigmoid): sa=0.5, ma=0.5, da=0.5
    //   p1 (g-gate, tanh):    sa=1,   ma=1,   da=0
    const float sa = (p == 1) ? 1.f : 0.5f;
    const float ma = (p == 1) ? 1.f : 0.5f;
    const float da = (p == 1) ? 0.f : 0.5f;

    // zero h parity 0 (both batches)
    if (j < 32) reinterpret_cast<float4*>(sh_h)[j] = make_float4(0.f, 0.f, 0.f, 0.f);

    // ---- x stream: depth-2 register prefetch, pointer-walk ----
    float  xcs = 0.f, xns = 0.f;                       // L0 scalar
    float2 xc2 = make_float2(0.f, 0.f), xn2 = xc2;     // !L0 packed pair
    const float*  xps = nullptr;
    const float2* xp2 = nullptr;
    if (L0) {
        const float* xbase = xin + (size_t)(b0 + b) * SS;
        xcs = xbase[0];
        xns = xbase[1];
        xps = xbase + 2;
    } else {
        const float2* xbase = reinterpret_cast<const float2*>(xin)
                              + ((size_t)(b0 + b) * SS) * 128 + hh * 2 + p;
        xc2 = xbase[0];
        xn2 = xbase[128];
        xp2 = xbase + 256;
    }
    __syncthreads();

    float c = 0.f;

    for (int t = 0; t < SS; ++t) {
        const int pr = t & 1;

        // ---- preload ALL of h (MLP 16) immediately after barrier ----
        ulonglong2 hb[16];
        {
            const ulonglong2* vh = reinterpret_cast<const ulonglong2*>(sh_h[pr][b]);
#pragma unroll
            for (int k = 0; k < 16; k++) hb[k] = vh[k];
        }

        // prefetch t+2 (pointer-walk, predicated tail) — overlaps LDS window
        float  pfs = 0.f;
        float2 pf2 = make_float2(0.f, 0.f);
        if (L0) { if (t + 2 < SS) pfs = *xps; xps += 1; }
        else    { if (t + 2 < SS) pf2 = *xp2; xp2 += 128; }

        // ax for this step
        float axA, axB;
        if (L0) { axA = fmaf(w0A, xcs, biasA); axB = fmaf(w0B, xcs, biasB); }
        else    { axA = xc2.x; axB = xc2.y; }

        // ---- four independent chains, depth 16 each (k-halves of 2 rows) ----
        ull a0a = pk2(axA, 0.f), a0b = pk2(0.f, 0.f);
        ull a1a = pk2(axB, 0.f), a1b = pk2(0.f, 0.f);
#pragma unroll
        for (int k = 0; k < 8; k++) {
            ulonglong2 hlo = hb[k];
            ulonglong2 hhi = hb[8 + k];
            a0a = ffma2(wA[2 * k], hlo.x, a0a);
            a0a = ffma2(wA[2 * k + 1], hlo.y, a0a);
            a0b = ffma2(wA[16 + 2 * k], hhi.x, a0b);
            a0b = ffma2(wA[17 + 2 * k], hhi.y, a0b);
            a1a = ffma2(wB[2 * k], hlo.x, a1a);
            a1a = ffma2(wB[2 * k + 1], hlo.y, a1a);
            a1b = ffma2(wB[16 + 2 * k], hhi.x, a1b);
            a1b = ffma2(wB[17 + 2 * k], hhi.y, a1b);
        }
        float l0, h0, l1, h1;
        upk2(a0a, l0, h0);
        upk2(a0b, l1, h1);
        float g0 = (l0 + h0) + (l1 + h1);
        upk2(a1a, l0, h0);
        upk2(a1b, l1, h1);
        float g1 = (l0 + h0) + (l1 + h1);

        // activations: single MUFU.TANH each (branchless constants)
        float A0 = fmaf(ma, tanh_mufu(sa * g0), da);            // i (sig) / g (tanh)
        float A1 = fmaf(0.5f, tanh_mufu(0.5f * g1), 0.5f);      // f / o (sigmoid)

        // pair exchange
        float B0 = __shfl_xor_sync(0xffffffffu, A0, 1);
        float B1 = __shfl_xor_sync(0xffffffffu, A1, 1);
        float iv, fv, gv, ov;
        if (p == 0) { iv = A0; fv = A1; gv = B0; ov = B1; }
        else        { iv = B0; fv = B1; gv = A0; ov = A1; }

        // identical update in both lanes (deterministic)
        c = fv * c + iv * gv;
        float hv2 = ov * tanh_mufu(c);

        // pre-barrier: ONLY the sh_h STS (BAR drains it)
        if (p == 0) {
            reinterpret_cast<float*>(sh_h[pr ^ 1][b])[hh] = hv2;
        }
        BATCH_BAR(b);   // this batch's 4 warps; h_t visible for t+1

        // post-barrier: global stores off the critical path
        if (p == 1) {
            hsout[((size_t)(b0 + b) * SS + t) * HH + hh] = hv2;
            if (t == SS - 1) {
                hn[(b0 + b) * HH + hh] = hv2;
                cn[(b0 + b) * HH + hh] = c;
            }
        }

        if (L0) { xcs = xns; xns = pfs; }
        else    { xc2 = xn2; xn2 = pf2; }
    }
}

// Final projection: thread-per-output, 16 consecutive LDG.128 per thread.
__global__ __launch_bounds__(256)
void proj_kernel(const float* __restrict__ hs, const float* __restrict__ Wlin,
                 const float* __restrict__ blin, float* __restrict__ y) {
    __shared__ float4 w[16];
    __shared__ float bsh;
    if (threadIdx.x < 16) w[threadIdx.x] = reinterpret_cast<const float4*>(Wlin)[threadIdx.x];
    if (threadIdx.x == 16) bsh = blin[0];
    __syncthreads();
    size_t o = (size_t)blockIdx.x * 256 + threadIdx.x;
    const float4* v = reinterpret_cast<const float4*>(hs + o * HH);
    float acc = 0.f;
#pragma unroll
    for (int k = 0; k < 16; k++) {
        float4 a = v[k];
        float4 b = w[k];
        acc += a.x * b.x + a.y * b.y + a.z * b.z + a.w * b.w;
    }
    y[o] = acc + bsh;
}

extern "C" void kernel_launch(void* const* d_in, const int* in_sizes, int n_in,
                              void* d_out, int out_size) {
    const float* x    = (const float*)d_in[0];
    const float* Wih0 = (const float*)d_in[1];
    const float* Whh0 = (const float*)d_in[2];
    const float* bih0 = (const float*)d_in[3];
    const float* bhh0 = (const float*)d_in[4];
    const float* Wih1 = (const float*)d_in[5];
    const float* Whh1 = (const float*)d_in[6];
    const float* bih1 = (const float*)d_in[7];
    const float* bhh1 = (const float*)d_in[8];
    const float* Wih2 = (const float*)d_in[9];
    const float* Whh2 = (const float*)d_in[10];
    const float* bih2 = (const float*)d_in[11];
    const float* bhh2 = (const float*)d_in[12];
    const float* Wlin = (const float*)d_in[13];
    const float* blin = (const float*)d_in[14];

    float* y  = (float*)d_out;                 // [B,S,1]
    float* hn = y + (size_t)BB * SS;           // [3,B,H]
    float* cn = hn + (size_t)3 * BB * HH;      // [3,B,H]

    float *buf0, *buf1, *xg;
    cudaGetSymbolAddress((void**)&buf0, g_buf0);
    cudaGetSymbolAddress((void**)&buf1, g_buf1);
    cudaGetSymbolAddress((void**)&xg,  g_xg);

    // Layer 0: inline scalar x (DIN=1)
    lstm_scan<true ><<<BB / 2, 256>>>(x, Wih0, Whh0, bih0, bhh0, buf0, hn, cn);
    // Layer 1: precompute interleaved xg (occ-2 grid), then h-only scan
    xgemm<<<1024, 256>>>(buf0, Wih1, bih1, bhh1, xg);
    lstm_scan<false><<<BB / 2, 256>>>(xg, Wih1, Whh1, bih1, bhh1, buf1,
                                      hn + BB * HH, cn + BB * HH);
    // Layer 2
    xgemm<<<1024, 256>>>(buf1, Wih2, bih2, bhh2, xg);
    lstm_scan<false><<<BB / 2, 256>>>(xg, Wih2, Whh2, bih2, bhh2, buf0,
                                      hn + 2 * BB * HH, cn + 2 * BB * HH);

    proj_kernel<<<(BB * SS) / 256, 256>>>(buf0, Wlin, blin, y);
}

// round 17
// speedup vs baseline: 1.0799x; 1.0799x over previous
#include <cuda_runtime.h>

#define BB 256
#define SS 4096
#define HH 64
#define NG 256   // 4*H gates

// Scratch (allocation-free: static device globals)
__device__ float g_buf0[(size_t)BB * SS * HH];
__device__ float g_buf1[(size_t)BB * SS * HH];
__device__ float g_xg[(size_t)BB * SS * NG];   // gate-interleaved: [b,s,hh*4+q]

typedef unsigned long long ull;

// ---- packed f32x2 helpers (FFMA2 path, sm_103a) ----
__device__ __forceinline__ ull pk2(float lo, float hi) {
    ull r; asm("mov.b64 %0,{%1,%2};" : "=l"(r) : "f"(lo), "f"(hi)); return r;
}
__device__ __forceinline__ void upk2(ull v, float& lo, float& hi) {
    asm("mov.b64 {%0,%1},%2;" : "=f"(lo), "=f"(hi) : "l"(v));
}
__device__ __forceinline__ ull ffma2(ull a, ull b, ull c) {
    ull d; asm("fma.rn.f32x2 %0,%1,%2,%3;" : "=l"(d) : "l"(a), "l"(b), "l"(c)); return d;
}

// single-op MUFU tanh (sm_75+). R13/R14 measured: total rel_err stays ~3e-6.
__device__ __forceinline__ float tanh_mufu(float x) {
    float r; asm("tanh.approx.f32 %0, %1;" : "=f"(r) : "f"(x)); return r;
}

// Named barrier over one batch's 128 threads (4 warps). ids 1,2.
#define BATCH_BAR(bl) asm volatile("bar.sync %0, 128;" :: "r"((bl) + 1) : "memory")

// ============================================================================
// xgemm v3: register-tiled outer product. R16 ncu: L1=93.6% (crossbar-bound,
// broadcast LDS.128 delivers 512B/instr). Fix: thread computes an 8-row x
// 4-gate tile so each loaded fragment feeds 64 FFMA2 per k-quad from 12 LDS
// (was 32 FFMA2 per 16 LDS). w is staged kq-major so its loads are
// lane-contiguous (conflict-free); h loads are warp-broadcast.
// Per-output accumulation: bias-seeded, ascending-k, lo=even/hi=odd pairs ->
// BITWISE IDENTICAL to the previous xgemm.
// Grid 2048 = pair(128) x slice(8) x ghalf(2); 256 thr; occ 2.
// ============================================================================
__global__ __launch_bounds__(256, 2)
void xgemm(const float* __restrict__ hs, const float* __restrict__ Wih,
           const float* __restrict__ bih, const float* __restrict__ bhh,
           float* __restrict__ xg) {
    const int t = threadIdx.x;
    const int gt = t & 31;            // gate-tile lane (32 per warp)
    const int rt = t >> 5;            // row-tile = warp id (8)
    const int pair = blockIdx.x >> 4;            // 0..127
    const int slice = (blockIdx.x >> 1) & 7;     // 0..7
    const int ghalf = blockIdx.x & 1;            // 0..1
    const int b0 = pair * 2;
    const int s0 = slice * (SS / 8);             // 512-step slice

    __shared__ float4 sw4[16][128];   // [kq][slot_local] : w_row(slot)[4kq..4kq+3]  (32KB)
    __shared__ float4 sh4[64][16];    // [row][kq] h chunk: 64 rows x 64 floats      (16KB)

    // ---- preamble: stage weights kq-major; compute per-slot biases ----
    {
        const int sl = t >> 1, half = t & 1;
        const int gs = ghalf * 128 + sl;
        const int wr = (gs & 3) * HH + (gs >> 2);   // PyTorch weight row for slot
        const float4* wsrc = reinterpret_cast<const float4*>(Wih + wr * HH);
#pragma unroll
        for (int i = 0; i < 8; i++) {
            const int kq = half * 8 + i;
            sw4[kq][sl] = wsrc[kq];
        }
    }
    float biasv[4];
#pragma unroll
    for (int c = 0; c < 4; c++) {
        const int gs = ghalf * 128 + 32 * c + gt;
        const int wr = (gs & 3) * HH + (gs >> 2);
        biasv[c] = bih[wr] + bhh[wr];
    }

    // h loader mapping: thread -> (row, float4-column)
    const int lrow = t >> 2;          // 0..63
    const int lqf = t & 3;            // 0..3
    const int lbb = lrow >> 5;        // batch within pair
    const int lsi = lrow & 31;        // s within 32-chunk
    const float4* hs4 = reinterpret_cast<const float4*>(hs);
    const size_t hbase = ((size_t)(b0 + lbb) * SS + s0 + lsi) * 16;

    __syncthreads();

    const int NCH = (SS / 8) / 32;    // 16 chunks of 32 s-steps (64 rows)
    for (int ch = 0; ch < NCH; ++ch) {
        // ---- load h chunk (coalesced LDG.128 -> STS.128) ----
        {
            const size_t base = hbase + (size_t)ch * 32 * 16;
#pragma unroll
            for (int i = 0; i < 4; i++)
                sh4[lrow][lqf + 4 * i] = hs4[base + lqf + 4 * i];
        }
        __syncthreads();

        // ---- compute 8x4 tile over K=64 ----
        ull acc[8][4];
#pragma unroll
        for (int r = 0; r < 8; r++)
#pragma unroll
            for (int c = 0; c < 4; c++)
                acc[r][c] = pk2(biasv[c], 0.f);

#pragma unroll
        for (int kq = 0; kq < 16; kq++) {
            ulonglong2 w4[4];
#pragma unroll
            for (int c = 0; c < 4; c++)
                w4[c] = *reinterpret_cast<const ulonglong2*>(&sw4[kq][32 * c + gt]);
#pragma unroll
            for (int r = 0; r < 8; r++) {
                ulonglong2 h2 = *reinterpret_cast<const ulonglong2*>(&sh4[rt * 8 + r][kq]);
#pragma unroll
                for (int c = 0; c < 4; c++) {
                    acc[r][c] = ffma2(w4[c].x, h2.x, acc[r][c]);
                    acc[r][c] = ffma2(w4[c].y, h2.y, acc[r][c]);
                }
            }
        }

        // ---- epilogue: horizontal add + coalesced STG.32 ----
#pragma unroll
        for (int r = 0; r < 8; r++) {
            const int row = rt * 8 + r;
            const int bb = row >> 5, si = row & 31;
            const size_t out = ((size_t)(b0 + bb) * SS + s0 + ch * 32 + si) * NG
                               + ghalf * 128 + gt;
#pragma unroll
            for (int c = 0; c < 4; c++) {
                float l, h;
                upk2(acc[r][c], l, h);
                xg[out + 32 * c] = l + h;
            }
        }
        __syncthreads();   // protect sh4 before next chunk's overwrite
    }
}

// ============================================================================
// LSTM scan = BYTE-EXACT R14/R15 champion (no changes).
// ============================================================================
template <bool L0>
__global__ __launch_bounds__(256, 1)
void lstm_scan(const float* __restrict__ xin,   // L0: x [B,S,1]; else xg [B,S,256]
               const float* __restrict__ Wih,   // L0 only: [256,1]
               const float* __restrict__ Whh,
               const float* __restrict__ bih, const float* __restrict__ bhh,
               float* __restrict__ hsout,
               float* __restrict__ hn, float* __restrict__ cn) {
    const int j = threadIdx.x;
    const int p = j & 1;
    const int hh = (j >> 1) & 63;
    const int b = j >> 7;
    const int b0 = blockIdx.x * 2;
    const int row0 = p * 128 + hh;        // p0: i-row ; p1: g-row
    const int row1 = p * 128 + 64 + hh;   // p0: f-row ; p1: o-row

    __shared__ float4 sh_h[2][2][16];   // [parity][b][64 floats]

    ull wA[32], wB[32];
    {
        const float4* Wr = reinterpret_cast<const float4*>(Whh + row0 * HH);
#pragma unroll
        for (int k = 0; k < 16; k++) {
            float4 v = Wr[k];
            wA[2 * k] = pk2(v.x, v.y);
            wA[2 * k + 1] = pk2(v.z, v.w);
        }
        const float4* Wr2 = reinterpret_cast<const float4*>(Whh + row1 * HH);
#pragma unroll
        for (int k = 0; k < 16; k++) {
            float4 v = Wr2[k];
            wB[2 * k] = pk2(v.x, v.y);
            wB[2 * k + 1] = pk2(v.z, v.w);
        }
    }
    float w0A = 0.f, w0B = 0.f, biasA = 0.f, biasB = 0.f;
    if (L0) {
        w0A = Wih[row0]; w0B = Wih[row1];
        biasA = bih[row0] + bhh[row0];
        biasB = bih[row1] + bhh[row1];
    }
    // activation constants: A0 = ma*tanh(sa*g0) + da
    const float sa = (p == 1) ? 1.f : 0.5f;
    const float ma = (p == 1) ? 1.f : 0.5f;
    const float da = (p == 1) ? 0.f : 0.5f;

    // zero h parity 0 (both batches)
    if (j < 32) reinterpret_cast<float4*>(sh_h)[j] = make_float4(0.f, 0.f, 0.f, 0.f);

    // ---- x stream: depth-2 register prefetch, pointer-walk ----
    float  xcs = 0.f, xns = 0.f;                       // L0 scalar
    float2 xc2 = make_float2(0.f, 0.f), xn2 = xc2;     // !L0 packed pair
    const float*  xps = nullptr;
    const float2* xp2 = nullptr;
    if (L0) {
        const float* xbase = xin + (size_t)(b0 + b) * SS;
        xcs = xbase[0];
        xns = xbase[1];
        xps = xbase + 2;
    } else {
        const float2* xbase = reinterpret_cast<const float2*>(xin)
                              + ((size_t)(b0 + b) * SS) * 128 + hh * 2 + p;
        xc2 = xbase[0];
        xn2 = xbase[128];
        xp2 = xbase + 256;
    }
    __syncthreads();

    float c = 0.f;

    for (int t = 0; t < SS; ++t) {
        const int pr = t & 1;

        // ---- preload ALL of h (MLP 16) immediately after barrier ----
        ulonglong2 hb[16];
        {
            const ulonglong2* vh = reinterpret_cast<const ulonglong2*>(sh_h[pr][b]);
#pragma unroll
            for (int k = 0; k < 16; k++) hb[k] = vh[k];
        }

        // prefetch t+2 (pointer-walk, predicated tail) — overlaps LDS window
        float  pfs = 0.f;
        float2 pf2 = make_float2(0.f, 0.f);
        if (L0) { if (t + 2 < SS) pfs = *xps; xps += 1; }
        else    { if (t + 2 < SS) pf2 = *xp2; xp2 += 128; }

        // ax for this step
        float axA, axB;
        if (L0) { axA = fmaf(w0A, xcs, biasA); axB = fmaf(w0B, xcs, biasB); }
        else    { axA = xc2.x; axB = xc2.y; }

        // ---- four independent chains, depth 16 each (k-halves of 2 rows) ----
        ull a0a = pk2(axA, 0.f), a0b = pk2(0.f, 0.f);
        ull a1a = pk2(axB, 0.f), a1b = pk2(0.f, 0.f);
#pragma unroll
        for (int k = 0; k < 8; k++) {
            ulonglong2 hlo = hb[k];
            ulonglong2 hhi = hb[8 + k];
            a0a = ffma2(wA[2 * k], hlo.x, a0a);
            a0a = ffma2(wA[2 * k + 1], hlo.y, a0a);
            a0b = ffma2(wA[16 + 2 * k], hhi.x, a0b);
            a0b = ffma2(wA[17 + 2 * k], hhi.y, a0b);
            a1a = ffma2(wB[2 * k], hlo.x, a1a);
            a1a = ffma2(wB[2 * k + 1], hlo.y, a1a);
            a1b = ffma2(wB[16 + 2 * k], hhi.x, a1b);
            a1b = ffma2(wB[17 + 2 * k], hhi.y, a1b);
        }
        float l0, h0, l1, h1;
        upk2(a0a, l0, h0);
        upk2(a0b, l1, h1);
        float g0 = (l0 + h0) + (l1 + h1);
        upk2(a1a, l0, h0);
        upk2(a1b, l1, h1);
        float g1 = (l0 + h0) + (l1 + h1);

        // activations: single MUFU.TANH each (branchless constants)
        float A0 = fmaf(ma, tanh_mufu(sa * g0), da);            // i (sig) / g (tanh)
        float A1 = fmaf(0.5f, tanh_mufu(0.5f * g1), 0.5f);      // f / o (sigmoid)

        // pair exchange
        float B0 = __shfl_xor_sync(0xffffffffu, A0, 1);
        float B1 = __shfl_xor_sync(0xffffffffu, A1, 1);
        float iv, fv, gv, ov;
        if (p == 0) { iv = A0; fv = A1; gv = B0; ov = B1; }
        else        { iv = B0; fv = B1; gv = A0; ov = A1; }

        // identical update in both lanes (deterministic)
        c = fv * c + iv * gv;
        float hv2 = ov * tanh_mufu(c);

        // pre-barrier: ONLY the sh_h STS (BAR drains it)
        if (p == 0) {
            reinterpret_cast<float*>(sh_h[pr ^ 1][b])[hh] = hv2;
        }
        BATCH_BAR(b);   // this batch's 4 warps; h_t visible for t+1

        // post-barrier: global stores off the critical path
        if (p == 1) {
            hsout[((size_t)(b0 + b) * SS + t) * HH + hh] = hv2;
            if (t == SS - 1) {
                hn[(b0 + b) * HH + hh] = hv2;
                cn[(b0 + b) * HH + hh] = c;
            }
        }

        if (L0) { xcs = xns; xns = pfs; }
        else    { xc2 = xn2; xn2 = pf2; }
    }
}

// Final projection: thread-per-output, 16 consecutive LDG.128 per thread.
__global__ __launch_bounds__(256)
void proj_kernel(const float* __restrict__ hs, const float* __restrict__ Wlin,
                 const float* __restrict__ blin, float* __restrict__ y) {
    __shared__ float4 w[16];
    __shared__ float bsh;
    if (threadIdx.x < 16) w[threadIdx.x] = reinterpret_cast<const float4*>(Wlin)[threadIdx.x];
    if (threadIdx.x == 16) bsh = blin[0];
    __syncthreads();
    size_t o = (size_t)blockIdx.x * 256 + threadIdx.x;
    const float4* v = reinterpret_cast<const float4*>(hs + o * HH);
    float acc = 0.f;
#pragma unroll
    for (int k = 0; k < 16; k++) {
        float4 a = v[k];
        float4 b = w[k];
        acc += a.x * b.x + a.y * b.y + a.z * b.z + a.w * b.w;
    }
    y[o] = acc + bsh;
}

extern "C" void kernel_launch(void* const* d_in, const int* in_sizes, int n_in,
                              void* d_out, int out_size) {
    const float* x    = (const float*)d_in[0];
    const float* Wih0 = (const float*)d_in[1];
    const float* Whh0 = (const float*)d_in[2];
    const float* bih0 = (const float*)d_in[3];
    const float* bhh0 = (const float*)d_in[4];
    const float* Wih1 = (const float*)d_in[5];
    const float* Whh1 = (const float*)d_in[6];
    const float* bih1 = (const float*)d_in[7];
    const float* bhh1 = (const float*)d_in[8];
    const float* Wih2 = (const float*)d_in[9];
    const float* Whh2 = (const float*)d_in[10];
    const float* bih2 = (const float*)d_in[11];
    const float* bhh2 = (const float*)d_in[12];
    const float* Wlin = (const float*)d_in[13];
    const float* blin = (const float*)d_in[14];

    float* y  = (float*)d_out;                 // [B,S,1]
    float* hn = y + (size_t)BB * SS;           // [3,B,H]
    float* cn = hn + (size_t)3 * BB * HH;      // [3,B,H]

    float *buf0, *buf1, *xg;
    cudaGetSymbolAddress((void**)&buf0, g_buf0);
    cudaGetSymbolAddress((void**)&buf1, g_buf1);
    cudaGetSymbolAddress((void**)&xg,  g_xg);

    // Layer 0: inline scalar x (DIN=1)
    lstm_scan<true ><<<BB / 2, 256>>>(x, Wih0, Whh0, bih0, bhh0, buf0, hn, cn);
    // Layer 1: precompute interleaved xg (register-tiled GEMM), then scan
    xgemm<<<2048, 256>>>(buf0, Wih1, bih1, bhh1, xg);
    lstm_scan<false><<<BB / 2, 256>>>(xg, Wih1, Whh1, bih1, bhh1, buf1,
                                      hn + BB * HH, cn + BB * HH);
    // Layer 2
    xgemm<<<2048, 256>>>(buf1, Wih2, bih2, bhh2, xg);
    lstm_scan<false><<<BB / 2, 256>>>(xg, Wih2, Whh2, bih2, bhh2, buf0,
                                      hn + 2 * BB * HH, cn + 2 * BB * HH);

    proj_kernel<<<(BB * SS) / 256, 256>>>(buf0, Wlin, blin, y);
}